// round 17
// baseline (speedup 1.0000x reference)
#include <cuda_runtime.h>
#include <cstdint>

// Problem constants
#define T_STEPS 512
#define BATCH   8
#define DDIM    512
#define NDIM    64
#define M_ROWS  (T_STEPS * BATCH)
#define E_COLS  1152
#define CLUSTER 4
#define DSLICE  128            // D per CTA

typedef unsigned long long u64;

// ---------------------------------------------------------------------------
// Scratch (no cudaMalloc allowed)
// ---------------------------------------------------------------------------
__device__ float g_k[M_ROWS * DDIM];
__device__ float g_q[M_ROWS * DDIM];
__device__ float g_wx[M_ROWS * NDIM];
__device__ float g_alpha[M_ROWS * NDIM];
__device__ float g_kq[M_ROWS];            // k_t . q_t
__device__ float g_kk2[M_ROWS];           // k_{t-1} . k_t   (0 at t=0)
__device__ float g_kqp[M_ROWS];           // k_{t-1} . q_t   (0 at t=0)

// ---------------------------------------------------------------------------
// Fast math helpers
// ---------------------------------------------------------------------------
__device__ __forceinline__ float tanh_f(float x) {
    float e = __expf(2.0f * x);
    return 1.0f - __fdividef(2.0f, e + 1.0f);
}
__device__ __forceinline__ float sigmoid_f(float x) {
    float e = __expf(-x);
    return __fdividef(1.0f, 1.0f + e);
}

// ---------------------------------------------------------------------------
// Cluster / mbarrier / async helpers
// ---------------------------------------------------------------------------
__device__ __forceinline__ uint32_t mapa_sh(uint32_t addr, int rank) {
    uint32_t d;
    asm("mapa.shared::cluster.u32 %0, %1, %2;" : "=r"(d) : "r"(addr), "r"(rank));
    return d;
}
__device__ __forceinline__ void mbar_init(uint32_t addr, uint32_t cnt) {
    asm volatile("mbarrier.init.shared.b64 [%0], %1;" :: "r"(addr), "r"(cnt) : "memory");
}
__device__ __forceinline__ void mbar_expect_tx(uint32_t addr, uint32_t bytes) {
    asm volatile("mbarrier.arrive.expect_tx.shared.b64 _, [%0], %1;"
                 :: "r"(addr), "r"(bytes) : "memory");
}
__device__ __forceinline__ void mbar_wait_parity(uint32_t addr, uint32_t parity) {
    asm volatile(
        "{\n\t"
        ".reg .pred P;\n\t"
        "WAIT_%=:\n\t"
        "mbarrier.try_wait.parity.acquire.cluster.shared::cta.b64 P, [%0], %1, 0x989680;\n\t"
        "@!P bra WAIT_%=;\n\t"
        "}"
        :: "r"(addr), "r"(parity) : "memory");
}
__device__ __forceinline__ void st_async_b64(uint32_t raddr, u64 val, uint32_t rmbar) {
    asm volatile("st.async.shared::cluster.mbarrier::complete_tx::bytes.b64 [%0], %1, [%2];"
                 :: "r"(raddr), "l"(val), "r"(rmbar) : "memory");
}
__device__ __forceinline__ u64 pack_f2(float lo, float hi) {
    u64 r;
    asm("mov.b64 %0, {%1, %2};" : "=l"(r) : "f"(lo), "f"(hi));
    return r;
}
__device__ __forceinline__ void cp_async16(uint32_t saddr, const void* gaddr) {
    asm volatile("cp.async.ca.shared.global [%0], [%1], 16;"
                 :: "r"(saddr), "l"(gaddr) : "memory");
}
#define CP_COMMIT() asm volatile("cp.async.commit_group;" ::: "memory")
#define CP_WAIT0()  asm volatile("cp.async.wait_group 0;" ::: "memory")
#define CP_WAIT1()  asm volatile("cp.async.wait_group 1;" ::: "memory")

// ---------------------------------------------------------------------------
// Kernel 1: fused projection GEMM (unchanged; ~125 us)
// ---------------------------------------------------------------------------
__global__ void __launch_bounds__(256)
proj_gemm_kernel(const float* __restrict__ x,
                 const float* __restrict__ Wk,
                 const float* __restrict__ Wq,
                 const float* __restrict__ Wx,
                 const float* __restrict__ Wa,
                 const float* __restrict__ ba)
{
    __shared__ float As[32][132];
    __shared__ float Bs[32][68];

    const int tid = threadIdx.x;
    const int m0 = blockIdx.x * 128;
    const int etile = blockIdx.y;

    const float* Wp;
    int erow0, mode;
    if (etile < 8)        { Wp = Wk; erow0 = etile * 64;        mode = 0; }
    else if (etile < 16)  { Wp = Wq; erow0 = (etile - 8) * 64;  mode = 1; }
    else if (etile == 16) { Wp = Wx; erow0 = 0;                 mode = 2; }
    else                  { Wp = Wa; erow0 = 0;                 mode = 3; }

    const int tx = tid & 15;
    const int ty = tid >> 4;

    float acc[8][4];
#pragma unroll
    for (int i = 0; i < 8; i++)
#pragma unroll
        for (int j = 0; j < 4; j++) acc[i][j] = 0.0f;

    const int arow = tid >> 3;
    const int acol = (tid & 7) * 4;
    const int brow = tid >> 2;
    const int bcol = (tid & 3) * 8;

    for (int k0 = 0; k0 < DDIM; k0 += 32) {
#pragma unroll
        for (int p = 0; p < 4; p++) {
            int r = arow + p * 32;
            float4 v = *(const float4*)(x + (size_t)(m0 + r) * DDIM + k0 + acol);
            As[acol + 0][r] = v.x;
            As[acol + 1][r] = v.y;
            As[acol + 2][r] = v.z;
            As[acol + 3][r] = v.w;
        }
        {
            const float* wrow = Wp + (size_t)(erow0 + brow) * DDIM + k0 + bcol;
            float4 v0 = *(const float4*)(wrow);
            float4 v1 = *(const float4*)(wrow + 4);
            Bs[bcol + 0][brow] = v0.x;
            Bs[bcol + 1][brow] = v0.y;
            Bs[bcol + 2][brow] = v0.z;
            Bs[bcol + 3][brow] = v0.w;
            Bs[bcol + 4][brow] = v1.x;
            Bs[bcol + 5][brow] = v1.y;
            Bs[bcol + 6][brow] = v1.z;
            Bs[bcol + 7][brow] = v1.w;
        }
        __syncthreads();

#pragma unroll
        for (int kk = 0; kk < 32; kk++) {
            float a[8];
            float4 a0 = *(const float4*)&As[kk][ty * 8];
            float4 a1 = *(const float4*)&As[kk][ty * 8 + 4];
            a[0] = a0.x; a[1] = a0.y; a[2] = a0.z; a[3] = a0.w;
            a[4] = a1.x; a[5] = a1.y; a[6] = a1.z; a[7] = a1.w;
            float4 bv = *(const float4*)&Bs[kk][tx * 4];
            float bj[4] = {bv.x, bv.y, bv.z, bv.w};
#pragma unroll
            for (int i = 0; i < 8; i++)
#pragma unroll
                for (int j = 0; j < 4; j++)
                    acc[i][j] = fmaf(a[i], bj[j], acc[i][j]);
        }
        __syncthreads();
    }

#pragma unroll
    for (int i = 0; i < 8; i++) {
        int m = m0 + ty * 8 + i;
#pragma unroll
        for (int j = 0; j < 4; j++) {
            int el = tx * 4 + j;
            float v = acc[i][j];
            if (mode == 0) {
                g_k[(size_t)m * DDIM + erow0 + el] = v;
            } else if (mode == 1) {
                g_q[(size_t)m * DDIM + erow0 + el] = v;
            } else if (mode == 2) {
                g_wx[(size_t)m * NDIM + el] = v;
            } else {
                g_alpha[(size_t)m * NDIM + el] = sigmoid_f(v + ba[el]);
            }
        }
    }
}

// ---------------------------------------------------------------------------
// Kernel 2: per-(t,b) scalars
// ---------------------------------------------------------------------------
__global__ void __launch_bounds__(256)
kq_kernel()
{
    int warp = threadIdx.x >> 5;
    int lane = threadIdx.x & 31;
    int row = blockIdx.x * 8 + warp;
    const bool has_prev = (row >= BATCH);
    const int prow = has_prev ? (row - BATCH) : row;
    const float* kp = g_k + (size_t)row * DDIM;
    const float* qp = g_q + (size_t)row * DDIM;
    const float* pp = g_k + (size_t)prow * DDIM;
    float akq = 0.0f, akk = 0.0f, akqp = 0.0f;
#pragma unroll
    for (int i = 0; i < DDIM / 32; i++) {
        int idx = i * 32 + lane;
        float kv = kp[idx], qv = qp[idx], pv = pp[idx];
        akq  = fmaf(kv, qv, akq);
        akk  = fmaf(pv, kv, akk);
        akqp = fmaf(pv, qv, akqp);
    }
#pragma unroll
    for (int off = 16; off > 0; off >>= 1) {
        akq  += __shfl_xor_sync(0xffffffffu, akq,  off);
        akk  += __shfl_xor_sync(0xffffffffu, akk,  off);
        akqp += __shfl_xor_sync(0xffffffffu, akqp, off);
    }
    if (lane == 0) {
        g_kq[row]  = akq;
        g_kk2[row] = has_prev ? akk  : 0.0f;
        g_kqp[row] = has_prev ? akqp : 0.0f;
    }
}

// ---------------------------------------------------------------------------
// Kernel 3: pipelined scan, cluster-4, pair-packed messages.
// 32 CTAs = 8 batches x 4 ranks; 512 threads: thread (n = tid>>3, g = tid&7)
// owns S[b, n, rank*128 + g*16 .. +16] (16 regs). k/q tiles live in a 4-deep
// SMEM ring fed by cp.async (no persistent k/q registers).
// Iter t: dots G_{t+1} = (S.k_{t+1}, S.q_{t+1}) -> pair-packed st.async.b64
// to 4 ranks (pq only to rank 0); wait buf t; reconstruct
//   Sk_t = a_{t-1}*SumG + c2_{t-1}*(k_{t-1}.k_t)   (exact one-step algebra)
// tanh -> rbuf -> Wr matvec -> v, alpha, c2; rank0 computes y; update S, STG.
// 4 recv bufs, parity (t>>2)&1; rbuf double-buffered; one __syncthreads/iter.
// ---------------------------------------------------------------------------
__global__ void __launch_bounds__(512, 1) __cluster_dims__(CLUSTER, 1, 1)
scan_kernel(const float* __restrict__ S0,
            const float* __restrict__ Wr,
            const float* __restrict__ bvec,
            float* __restrict__ outY,
            float* __restrict__ outS)
{
    __shared__ float recvPK[4][CLUSTER][68];   // [buf][src][n] (+pad)
    __shared__ float recvPQ[4][CLUSTER][68];   // written only on rank 0
    __shared__ float rbuf[2][NDIM];
    __shared__ alignas(16) float ktile[4][DSLICE];
    __shared__ alignas(16) float qtile[4][DSLICE];
    __shared__ alignas(8) u64 mbar[4];

    const int tid  = threadIdx.x;
    const int n    = tid >> 3;           // 0..63
    const int g    = tid & 7;            // 0..7
    const int b    = blockIdx.x >> 2;
    const int rank = blockIdx.x & 3;
    const int dbase = rank * DSLICE + g * 16;

    const uint32_t recvPK_base = (uint32_t)__cvta_generic_to_shared(&recvPK[0][0][0]);
    const uint32_t recvPQ_base = (uint32_t)__cvta_generic_to_shared(&recvPQ[0][0][0]);
    const uint32_t mbar_base   = (uint32_t)__cvta_generic_to_shared(&mbar[0]);
    const uint32_t ktile_base  = (uint32_t)__cvta_generic_to_shared(&ktile[0][0]);
    const uint32_t qtile_base  = (uint32_t)__cvta_generic_to_shared(&qtile[0][0]);

    // incoming bytes per buf: pk = 4 srcs * 64 n * 4B = 1024; rank0 also pq.
    const uint32_t EXP = (rank == 0) ? 2048u : 1024u;

    if (tid == 0) {
#pragma unroll
        for (int s = 0; s < 4; s++) mbar_init(mbar_base + s * 8, 1);
#pragma unroll
        for (int s = 0; s < 4; s++) mbar_expect_tx(mbar_base + s * 8, EXP);
    }
    __syncthreads();
    asm volatile("barrier.cluster.arrive.aligned;" ::: "memory");
    asm volatile("barrier.cluster.wait.aligned;" ::: "memory");

    // Persistent registers: S slice + Wr row-slice
    float S[16], Wreg[8];
#pragma unroll
    for (int j = 0; j < 8; j += 4) {
        float4 v = *(const float4*)(Wr + n * NDIM + g * 8 + j);
        Wreg[j] = v.x; Wreg[j + 1] = v.y; Wreg[j + 2] = v.z; Wreg[j + 3] = v.w;
    }
    const float breg = bvec[n];

    // S0 slice; emit as outS index 0
    {
        const float* s0p = S0 + ((size_t)b * NDIM + n) * DDIM + dbase;
        float* so = outS + ((size_t)b * NDIM + n) * DDIM + dbase;
#pragma unroll
        for (int j = 0; j < 16; j += 4) {
            float4 v = *(const float4*)(s0p + j);
            S[j] = v.x; S[j + 1] = v.y; S[j + 2] = v.z; S[j + 3] = v.w;
            *(float4*)(so + j) = v;
        }
    }

    // Stage k/q rows 0 and 1 into ring slots 0,1
    if (tid < 128) {
        int which = (tid >> 5) & 1;   // 0:k 1:q
        int slot  = tid >> 6;         // 0 or 1
        int c     = tid & 31;         // 16B chunk
        size_t row = (size_t)slot * BATCH + b;
        const float* src = (which ? g_q : g_k) + row * DDIM + rank * DSLICE + c * 4;
        uint32_t dst = (which ? qtile_base : ktile_base)
                     + (uint32_t)((slot * DSLICE + c * 4) * 4);
        cp_async16(dst, src);
    }
    if (tid < 128) { CP_COMMIT(); CP_WAIT0(); }
    __syncthreads();

    // Pre-push G_0 = (S0.k_0, S0.q_0) into buf 0 (pair-packed)
    {
        const float* ks = &ktile[0][g * 16];
        const float* qs = &qtile[0][g * 16];
        float pk = 0.0f, pq = 0.0f;
#pragma unroll
        for (int j = 0; j < 16; j++) {
            pk = fmaf(S[j], ks[j], pk);
            pq = fmaf(S[j], qs[j], pq);
        }
        pk += __shfl_xor_sync(0xffffffffu, pk, 1);
        pk += __shfl_xor_sync(0xffffffffu, pk, 2);
        pk += __shfl_xor_sync(0xffffffffu, pk, 4);
        pq += __shfl_xor_sync(0xffffffffu, pq, 1);
        pq += __shfl_xor_sync(0xffffffffu, pq, 2);
        pq += __shfl_xor_sync(0xffffffffu, pq, 4);
        float pk_hi = __shfl_down_sync(0xffffffffu, pk, 8);
        float pq_hi = __shfl_down_sync(0xffffffffu, pq, 8);
        if (g == 0 && (n & 1) == 0) {
            u64 vk = pack_f2(pk, pk_hi);
            u64 vq = pack_f2(pq, pq_hi);
            uint32_t la = recvPK_base + (uint32_t)(((0 * CLUSTER + rank) * 68 + n) * 4);
            uint32_t lq = recvPQ_base + (uint32_t)(((0 * CLUSTER + rank) * 68 + n) * 4);
            uint32_t lm = mbar_base;
#pragma unroll
            for (int r = 0; r < CLUSTER; r++)
                st_async_b64(mapa_sh(la, r), vk, mapa_sh(lm, r));
            st_async_b64(mapa_sh(lq, 0), vq, mapa_sh(lm, 0));
        }
    }

    // Scalars for t=0
    float alc, wxc, kqc, kk2c, kqpc;
    {
        const size_t row0 = (size_t)b;
        alc  = g_alpha[row0 * NDIM + n];
        wxc  = g_wx[row0 * NDIM + n];
        kqc  = g_kq[row0];
        kk2c = g_kk2[row0];   // = 0
        kqpc = g_kqp[row0];   // = 0
    }

    float a_prev = 1.0f, c2_prev = 0.0f;

    for (int t = 0; t < T_STEPS; t++) {
        // 0) issue cp.async for k/q row t+2 into ring slot (t+2)&3
        if (tid < 64) {
            if (t + 2 < T_STEPS) {
                int which = tid >> 5;     // 0:k 1:q
                int c     = tid & 31;
                int slot  = (t + 2) & 3;
                size_t row = (size_t)(t + 2) * BATCH + b;
                const float* src = (which ? g_q : g_k) + row * DDIM + rank * DSLICE + c * 4;
                uint32_t dst = (which ? qtile_base : ktile_base)
                             + (uint32_t)((slot * DSLICE + c * 4) * 4);
                cp_async16(dst, src);
            }
            CP_COMMIT();
        }

        // 1) dots G_{t+1} from S and ring slot (t+1)&3; pair-pack; push
        {
            const int dslot = (t + 1) & 3;
            const float* ks = &ktile[dslot][g * 16];
            const float* qs = &qtile[dslot][g * 16];
            float pk = 0.0f, pq = 0.0f;
#pragma unroll
            for (int j = 0; j < 16; j++) {
                pk = fmaf(S[j], ks[j], pk);
                pq = fmaf(S[j], qs[j], pq);
            }
            pk += __shfl_xor_sync(0xffffffffu, pk, 1);
            pk += __shfl_xor_sync(0xffffffffu, pk, 2);
            pk += __shfl_xor_sync(0xffffffffu, pk, 4);
            pq += __shfl_xor_sync(0xffffffffu, pq, 1);
            pq += __shfl_xor_sync(0xffffffffu, pq, 2);
            pq += __shfl_xor_sync(0xffffffffu, pq, 4);
            float pk_hi = __shfl_down_sync(0xffffffffu, pk, 8);
            float pq_hi = __shfl_down_sync(0xffffffffu, pq, 8);
            if ((t + 1 < T_STEPS) && g == 0 && (n & 1) == 0) {
                const int dbuf = (t + 1) & 3;
                u64 vk = pack_f2(pk, pk_hi);
                u64 vq = pack_f2(pq, pq_hi);
                uint32_t la = recvPK_base + (uint32_t)(((dbuf * CLUSTER + rank) * 68 + n) * 4);
                uint32_t lq = recvPQ_base + (uint32_t)(((dbuf * CLUSTER + rank) * 68 + n) * 4);
                uint32_t lm = mbar_base + (uint32_t)(dbuf * 8);
#pragma unroll
                for (int r = 0; r < CLUSTER; r++)
                    st_async_b64(mapa_sh(la, r), vk, mapa_sh(lm, r));
                st_async_b64(mapa_sh(lq, 0), vq, mapa_sh(lm, 0));
            }
        }

        // 2) prefetch scalars for t+1 (clamped)
        float aln, wxn, kqn, kk2n, kqpn;
        {
            const int t1 = (t + 1 < T_STEPS) ? (t + 1) : (T_STEPS - 1);
            const size_t row1 = (size_t)t1 * BATCH + b;
            aln  = g_alpha[row1 * NDIM + n];
            wxn  = g_wx[row1 * NDIM + n];
            kqn  = g_kq[row1];
            kk2n = g_kk2[row1];
            kqpn = g_kqp[row1];
        }

        // 3) wait for step t's gather; re-arm for step t+4
        const int wbuf = t & 3;
        mbar_wait_parity(mbar_base + (uint32_t)(wbuf * 8), (uint32_t)((t >> 2) & 1));
        if (tid == 0) mbar_expect_tx(mbar_base + (uint32_t)(wbuf * 8), EXP);

        // 4) sum 4 src-partials (lanes g&3 read distinct srcs; xor 1,2) + correction
        float skG = recvPK[wbuf][g & 3][n];
        skG += __shfl_xor_sync(0xffffffffu, skG, 1);
        skG += __shfl_xor_sync(0xffffffffu, skG, 2);
        const float sk = fmaf(a_prev, skG, c2_prev * kk2c);
        float sq = 0.0f;
        if (rank == 0) {
            float sqG = recvPQ[wbuf][g & 3][n];
            sqG += __shfl_xor_sync(0xffffffffu, sqG, 1);
            sqG += __shfl_xor_sync(0xffffffffu, sqG, 2);
            sq = fmaf(a_prev, sqG, c2_prev * kqpc);
        }

        // 4.5) drain cp.async so slot (t+1) is ready for next iter (barrier below
        //      publishes it to all threads)
        if (tid < 64) CP_WAIT1();

        // 5) r_t = tanh(Sk); broadcast; Wr matvec
        const int rb = t & 1;
        float rn = tanh_f(sk);
        if (g == 0) rbuf[rb][n] = rn;
        __syncthreads();

        float accv = 0.0f;
        {
            const float* rp = &rbuf[rb][g * 8];
#pragma unroll
            for (int j = 0; j < 8; j++)
                accv = fmaf(Wreg[j], rp[j], accv);
        }
        accv += __shfl_xor_sync(0xffffffffu, accv, 1);
        accv += __shfl_xor_sync(0xffffffffu, accv, 2);
        accv += __shfl_xor_sync(0xffffffffu, accv, 4);

        const float v  = tanh_f(accv + wxc + breg);
        const float al = alc;
        const float c2 = (1.0f - al) * v;

        // 6) y_t on rank 0 only (it is identical across ranks)
        if (rank == 0 && g == 0) {
            float y = tanh_f(fmaf(al, sq, c2 * kqc));
            outY[((size_t)t * BATCH + b) * NDIM + n] = y;
        }

        // 7) state update with k_t (ring slot t&3) + store S_{t+1}
        {
            const float* ku = &ktile[t & 3][g * 16];
#pragma unroll
            for (int j = 0; j < 16; j++)
                S[j] = fmaf(al, S[j], c2 * ku[j]);
            float* sp = outS + (((size_t)(t + 1) * BATCH + b) * NDIM + n) * DDIM + dbase;
#pragma unroll
            for (int j = 0; j < 16; j += 4)
                *(float4*)(sp + j) = make_float4(S[j], S[j + 1], S[j + 2], S[j + 3]);
        }

        // 8) rotate
        a_prev = al; c2_prev = c2;
        alc = aln; wxc = wxn; kqc = kqn; kk2c = kk2n; kqpc = kqpn;
    }

    __syncthreads();
    asm volatile("barrier.cluster.arrive.aligned;" ::: "memory");
    asm volatile("barrier.cluster.wait.aligned;" ::: "memory");
}

// ---------------------------------------------------------------------------
// Launch
// Inputs (metadata order): x, S0, W_k, W_q, W_x, W_r, b, W_alpha, b_alpha
// Output: concat(output [T,B,N], S [T+1,B,N,D]) as float32
// ---------------------------------------------------------------------------
extern "C" void kernel_launch(void* const* d_in, const int* in_sizes, int n_in,
                              void* d_out, int out_size)
{
    const float* x   = (const float*)d_in[0];
    const float* S0  = (const float*)d_in[1];
    const float* Wk  = (const float*)d_in[2];
    const float* Wq  = (const float*)d_in[3];
    const float* Wx  = (const float*)d_in[4];
    const float* Wrm = (const float*)d_in[5];
    const float* bv  = (const float*)d_in[6];
    const float* Wa  = (const float*)d_in[7];
    const float* ba  = (const float*)d_in[8];

    float* outY = (float*)d_out;
    float* outS = outY + (size_t)T_STEPS * BATCH * NDIM;

    dim3 gemm_grid(M_ROWS / 128, E_COLS / 64);  // (32, 18)
    proj_gemm_kernel<<<gemm_grid, 256>>>(x, Wk, Wq, Wx, Wa, ba);
    kq_kernel<<<M_ROWS / 8, 256>>>();
    scan_kernel<<<BATCH * CLUSTER, 512>>>(S0, Wrm, bv, outY, outS);
}